// round 4
// baseline (speedup 1.0000x reference)
#include <cuda_runtime.h>
#include <cstdint>

// Problem constants
#define NHEADS 16
#define DHEAD  128
#define SEQ    2048
#define BATCH  4
#define DIM    2048
#define BHTOT  (BATCH * NHEADS)   // 64

// Scratch (device globals: allocation-free per harness rules) — 256 MiB total
__device__ float g_Q[(size_t)BHTOT * SEQ * DHEAD];          // [bh][n][d]   (tf32-rounded after rope)
__device__ float g_K[(size_t)BHTOT * SEQ * DHEAD];          // [bh][n][d]   (tf32-rounded after rope)
__device__ float g_V[(size_t)BHTOT * DHEAD * SEQ];          // [bh][d][n]   (tf32-rounded, transposed)
__device__ float g_O[(size_t)BATCH * SEQ * DIM];            // [b][n][h*d]  (fp32)

// ---------------------------------------------------------------------------
// TF32 / cp.async helpers
// ---------------------------------------------------------------------------
__device__ __forceinline__ uint32_t f2tf32(float f) {
    uint32_t r;
    asm("cvt.rna.tf32.f32 %0, %1;" : "=r"(r) : "f"(f));
    return r;
}
__device__ __forceinline__ float f2tf32f(float f) { return __uint_as_float(f2tf32(f)); }

__device__ __forceinline__ void mma_tf32(float* c, const uint32_t* a, uint32_t b0, uint32_t b1) {
    asm volatile(
        "mma.sync.aligned.m16n8k8.row.col.f32.tf32.tf32.f32 "
        "{%0,%1,%2,%3}, {%4,%5,%6,%7}, {%8,%9}, {%0,%1,%2,%3};\n"
        : "+f"(c[0]), "+f"(c[1]), "+f"(c[2]), "+f"(c[3])
        : "r"(a[0]), "r"(a[1]), "r"(a[2]), "r"(a[3]), "r"(b0), "r"(b1));
}

__device__ __forceinline__ void cp16(float* s, const float* g) {
    uint32_t sa = (uint32_t)__cvta_generic_to_shared(s);
    asm volatile("cp.async.cg.shared.global [%0], [%1], 16;\n" :: "r"(sa), "l"(g));
}
#define CP_COMMIT() asm volatile("cp.async.commit_group;\n" ::: "memory")
#define CP_WAIT1()  asm volatile("cp.async.wait_group 1;\n" ::: "memory")
#define CP_WAIT0()  asm volatile("cp.async.wait_group 0;\n" ::: "memory")

// ---------------------------------------------------------------------------
// NT GEMM: C[M,N] = A[M,K] * B[N,K]^T  (row-major, K contiguous).
// Tile 128x128, BK=32, 2-stage cp.async pipeline, dynamic smem (72 KB).
// After each stage lands, one convert-in-place pass rounds the tile to tf32;
// the MMA mainloop then does raw LDS + MMA only.
// 8 warps (4 along M x 2 along N), warp 32x64 via 2x8 m16n8k8 TF32 tiles.
// MODE 0: A=x, B=w_qkv -> scatter g_Q / g_K (raw; rope rounds) / g_V (rounded)
// MODE 3: A=g_O, B=w_out, +bias -> d_out
// ---------------------------------------------------------------------------
#define BM 128
#define BN 128
#define BK 32
#define BKP 36   // padded smem row stride in floats (multiple of 4 for STS.128)
#define GEMM_SMEM_FLOATS (4 * BM * BKP)          // As[2] + Bs[2]
#define GEMM_SMEM_BYTES  (GEMM_SMEM_FLOATS * 4)  // 73,728

template <int MODE>
__global__ __launch_bounds__(256)
void gemm_nt(const float* __restrict__ Ain, const float* __restrict__ Bin,
             const float* __restrict__ bias, float* __restrict__ Cout,
             int M, int N, int K)
{
    extern __shared__ float sg[];
    float* const Abuf[2] = { sg,            sg + BM * BKP };
    float* const Bbuf[2] = { sg + 2 * BM * BKP, sg + 3 * BM * BKP };

    const int tid  = threadIdx.x;
    const int lane = tid & 31;
    const int wid  = tid >> 5;
    const int g    = lane >> 2;
    const int tig  = lane & 3;
    const int wm   = wid & 3;
    const int wn   = wid >> 2;
    const int bm   = blockIdx.y;
    const int bn   = blockIdx.x;

    const float* A = (MODE == 3) ? g_O : Ain;
    const float* B = Bin;
    const float* Abase = A + (size_t)(bm * BM) * K;
    const float* Bbase = B + (size_t)(bn * BN) * K;

    float acc[2][8][4];
    #pragma unroll
    for (int mt = 0; mt < 2; mt++)
        #pragma unroll
        for (int nt = 0; nt < 8; nt++)
            #pragma unroll
            for (int i = 0; i < 4; i++) acc[mt][nt][i] = 0.f;

    const int KT = K / BK;

    // per-thread copy slots: 4 float4 per matrix per stage
    // e = i*256 + tid ; row = e>>3 (0..127) ; c4 = e&7 (float4 within 32-col row)
    #pragma unroll
    for (int i = 0; i < 4; i++) {
        int e = i * 256 + tid;
        int row = e >> 3, c4 = e & 7;
        cp16(&Abuf[0][row * BKP + c4 * 4], Abase + (size_t)row * K + c4 * 4);
        cp16(&Bbuf[0][row * BKP + c4 * 4], Bbase + (size_t)row * K + c4 * 4);
    }
    CP_COMMIT();

    for (int kt = 0; kt < KT; kt++) {
        const int cur = kt & 1;
        if (kt + 1 < KT) {
            const int nxt = cur ^ 1;
            const int k1 = (kt + 1) * BK;
            #pragma unroll
            for (int i = 0; i < 4; i++) {
                int e = i * 256 + tid;
                int row = e >> 3, c4 = e & 7;
                cp16(&Abuf[nxt][row * BKP + c4 * 4], Abase + (size_t)row * K + k1 + c4 * 4);
                cp16(&Bbuf[nxt][row * BKP + c4 * 4], Bbase + (size_t)row * K + k1 + c4 * 4);
            }
            CP_COMMIT();
            CP_WAIT1();
        } else {
            CP_WAIT0();
        }
        __syncthreads();

        // ---- convert-in-place: round this stage to tf32 once ----
        #pragma unroll
        for (int i = 0; i < 4; i++) {
            int e = i * 256 + tid;
            int off = (e >> 3) * BKP + (e & 7) * 4;
            float4 va = *(float4*)&Abuf[cur][off];
            va.x = f2tf32f(va.x); va.y = f2tf32f(va.y);
            va.z = f2tf32f(va.z); va.w = f2tf32f(va.w);
            *(float4*)&Abuf[cur][off] = va;
            float4 vb = *(float4*)&Bbuf[cur][off];
            vb.x = f2tf32f(vb.x); vb.y = f2tf32f(vb.y);
            vb.z = f2tf32f(vb.z); vb.w = f2tf32f(vb.w);
            *(float4*)&Bbuf[cur][off] = vb;
        }
        __syncthreads();

        const float* As = Abuf[cur];
        const float* Bs = Bbuf[cur];
        #pragma unroll
        for (int ks = 0; ks < 4; ks++) {
            uint32_t afr[2][4];
            #pragma unroll
            for (int mt = 0; mt < 2; mt++) {
                int r0 = wm * 32 + mt * 16 + g;
                int c0 = ks * 8 + tig;
                afr[mt][0] = __float_as_uint(As[r0 * BKP + c0]);
                afr[mt][1] = __float_as_uint(As[(r0 + 8) * BKP + c0]);
                afr[mt][2] = __float_as_uint(As[r0 * BKP + c0 + 4]);
                afr[mt][3] = __float_as_uint(As[(r0 + 8) * BKP + c0 + 4]);
            }
            #pragma unroll
            for (int nt = 0; nt < 8; nt++) {
                int nr = wn * 64 + nt * 8 + g;
                int kc = ks * 8 + tig;
                uint32_t b0 = __float_as_uint(Bs[nr * BKP + kc]);
                uint32_t b1 = __float_as_uint(Bs[nr * BKP + kc + 4]);
                #pragma unroll
                for (int mt = 0; mt < 2; mt++)
                    mma_tf32(acc[mt][nt], afr[mt], b0, b1);
            }
        }
        __syncthreads();
    }

    #pragma unroll
    for (int mt = 0; mt < 2; mt++) {
        #pragma unroll
        for (int nt = 0; nt < 8; nt++) {
            int row0 = bm * BM + wm * 32 + mt * 16 + g;
            int col  = bn * BN + wn * 64 + nt * 8 + 2 * tig;
            #pragma unroll
            for (int rr = 0; rr < 2; rr++) {
                int row = row0 + rr * 8;
                float x0 = acc[mt][nt][rr * 2 + 0];
                float x1 = acc[mt][nt][rr * 2 + 1];
                if (MODE == 0) {
                    int b = row >> 11, pos = row & 2047;
                    int which = col >> 11, rem = col & 2047;
                    int h = rem >> 7, d = rem & 127;
                    int bhh = (b << 4) + h;
                    if (which == 2) {
                        // V: pre-round to tf32 so flash never converts
                        g_V[((size_t)bhh * DHEAD + d)     * SEQ + pos] = f2tf32f(x0);
                        g_V[((size_t)bhh * DHEAD + d + 1) * SEQ + pos] = f2tf32f(x1);
                    } else if (which == 0) {
                        *(float2*)(g_Q + ((size_t)bhh * SEQ + pos) * DHEAD + d) = make_float2(x0, x1);
                    } else {
                        *(float2*)(g_K + ((size_t)bhh * SEQ + pos) * DHEAD + d) = make_float2(x0, x1);
                    }
                } else {
                    *(float2*)(Cout + (size_t)row * N + col) =
                        make_float2(x0 + bias[col], x1 + bias[col + 1]);
                }
            }
        }
    }
}

// ---------------------------------------------------------------------------
// RoPE: in-place on g_Q, g_K; writes tf32-rounded bits (single rounding point
// for the attention MMAs).
// ---------------------------------------------------------------------------
__global__ __launch_bounds__(256)
void rope_kernel()
{
    int t = blockIdx.x * blockDim.x + threadIdx.x;   // 64*2048*64 threads
    int i   = t & 63;
    int pos = (t >> 6) & 2047;
    int bh  = t >> 17;
    float p = (float)(2 * i) * (1.0f / 128.0f);
    float inv_freq = powf(10000.0f, -p);
    float fr = (float)pos * inv_freq;
    float s, c;
    sincosf(fr, &s, &c);
    size_t base = ((size_t)bh * SEQ + pos) * DHEAD;

    float q1 = g_Q[base + i], q2 = g_Q[base + i + 64];
    g_Q[base + i]      = f2tf32f(q1 * c - q2 * s);
    g_Q[base + i + 64] = f2tf32f(q2 * c + q1 * s);

    float k1 = g_K[base + i], k2 = g_K[base + i + 64];
    g_K[base + i]      = f2tf32f(k1 * c - k2 * s);
    g_K[base + i + 64] = f2tf32f(k2 * c + k1 * s);
}

// ---------------------------------------------------------------------------
// Fused flash attention: per block = (q-tile of 128 rows, bh).
// 8 warps x 16 q-rows; row reductions are shfl.bfly within 4-lane groups.
// Q register-resident. K/V pre-rounded tf32 in HBM -> mainloop is raw
// LDS + MMA (zero CVTs). K/V double-buffered cp.async. P routed through smem
// (tf32-pre-rounded) to re-enter as A-fragments.
// ---------------------------------------------------------------------------
#define TKV 64
#define NKVT (SEQ / TKV)     // 32
#define KST 132              // smem stride for K/Q tile rows (128 cols + pad)
#define VST 68               // smem stride for V/P tile rows (64 cols + pad)
// smem (floats): sK[2][64*132]=16896, sV[2][128*68]=17408, sP[128*68]=8704
#define FLASH_SMEM_FLOATS (16896 + 17408 + 8704)
#define FLASH_SMEM_BYTES  (FLASH_SMEM_FLOATS * 4)   // 172,032

__global__ __launch_bounds__(256)
void flash_kernel()
{
    extern __shared__ float sm[];
    float* const sK0 = sm;
    float* const sK1 = sm + 8448;
    float* const sV0 = sm + 16896;
    float* const sV1 = sm + 25600;
    float* const sP  = sm + 34304;

    const int tid  = threadIdx.x;
    const int lane = tid & 31;
    const int wid  = tid >> 5;
    const int g    = lane >> 2;
    const int tig  = lane & 3;
    const int bh   = blockIdx.y;
    const int q0   = blockIdx.x * 128;
    const float scale = 0.08838834764831845f;  // 128^-0.5

    const float* Qg = g_Q + (size_t)bh * SEQ * DHEAD;
    const float* Kg = g_K + (size_t)bh * SEQ * DHEAD;
    const float* Vg = g_V + (size_t)bh * DHEAD * SEQ;

    // ---- stage Q tile (128x128) through smem, extract A-fragments ----
    #pragma unroll
    for (int i = 0; i < 16; i++) {
        int e = i * 256 + tid;            // float4 index over 128 rows x 32
        int row = e >> 5, c4 = e & 31;
        cp16(&sm[row * KST + c4 * 4], Qg + (size_t)(q0 + row) * DHEAD + c4 * 4);
    }
    CP_COMMIT();
    CP_WAIT0();
    __syncthreads();

    const int r0 = wid * 16 + g;          // this thread's first q row (local)
    uint32_t qf[16][4];
    #pragma unroll
    for (int kt = 0; kt < 16; kt++) {
        qf[kt][0] = __float_as_uint(sm[r0 * KST + kt * 8 + tig]);
        qf[kt][1] = __float_as_uint(sm[(r0 + 8) * KST + kt * 8 + tig]);
        qf[kt][2] = __float_as_uint(sm[r0 * KST + kt * 8 + tig + 4]);
        qf[kt][3] = __float_as_uint(sm[(r0 + 8) * KST + kt * 8 + tig + 4]);
    }
    __syncthreads();

    float oacc[16][4];
    #pragma unroll
    for (int nt = 0; nt < 16; nt++)
        #pragma unroll
        for (int i = 0; i < 4; i++) oacc[nt][i] = 0.f;
    float mrow0 = -1e30f, mrow1 = -1e30f;
    float lrow0 = 0.f, lrow1 = 0.f;

    // prologue: tile 0 into buffer 0
    {
        #pragma unroll
        for (int i = 0; i < 8; i++) {
            int e = i * 256 + tid;
            int kr = e >> 5, kc = e & 31;       // K: 64 rows x 32 float4
            cp16(&sK0[kr * KST + kc * 4], Kg + (size_t)kr * DHEAD + kc * 4);
            int vr = e >> 4, vc = e & 15;       // V: 128 rows x 16 float4
            cp16(&sV0[vr * VST + vc * 4], Vg + (size_t)vr * SEQ + vc * 4);
        }
        CP_COMMIT();
    }

    for (int it = 0; it < NKVT; it++) {
        const int buf = it & 1;
        const float* sK = buf ? sK1 : sK0;
        const float* sV = buf ? sV1 : sV0;

        if (it + 1 < NKVT) {
            float* dK = buf ? sK0 : sK1;
            float* dV = buf ? sV0 : sV1;
            const int kv1 = (it + 1) * TKV;
            #pragma unroll
            for (int i = 0; i < 8; i++) {
                int e = i * 256 + tid;
                int kr = e >> 5, kc = e & 31;
                cp16(&dK[kr * KST + kc * 4], Kg + (size_t)(kv1 + kr) * DHEAD + kc * 4);
                int vr = e >> 4, vc = e & 15;
                cp16(&dV[vr * VST + vc * 4], Vg + (size_t)vr * SEQ + kv1 + vc * 4);
            }
            CP_COMMIT();
            CP_WAIT1();
        } else {
            CP_WAIT0();
        }
        __syncthreads();

        // ---- S = Q K^T for this warp's 16 rows x 64 kv cols ----
        float sacc[8][4];
        #pragma unroll
        for (int nt = 0; nt < 8; nt++)
            #pragma unroll
            for (int i = 0; i < 4; i++) sacc[nt][i] = 0.f;

        #pragma unroll
        for (int kt = 0; kt < 16; kt++) {
            #pragma unroll
            for (int nt = 0; nt < 8; nt++) {
                uint32_t b0 = __float_as_uint(sK[(nt * 8 + g) * KST + kt * 8 + tig]);
                uint32_t b1 = __float_as_uint(sK[(nt * 8 + g) * KST + kt * 8 + tig + 4]);
                mma_tf32(sacc[nt], qf[kt], b0, b1);
            }
        }

        // ---- online softmax (rows r0 and r0+8) ----
        float tm0 = -1e30f, tm1 = -1e30f;
        #pragma unroll
        for (int nt = 0; nt < 8; nt++) {
            tm0 = fmaxf(tm0, fmaxf(sacc[nt][0], sacc[nt][1]));
            tm1 = fmaxf(tm1, fmaxf(sacc[nt][2], sacc[nt][3]));
        }
        tm0 = fmaxf(tm0, __shfl_xor_sync(0xffffffffu, tm0, 1));
        tm0 = fmaxf(tm0, __shfl_xor_sync(0xffffffffu, tm0, 2));
        tm1 = fmaxf(tm1, __shfl_xor_sync(0xffffffffu, tm1, 1));
        tm1 = fmaxf(tm1, __shfl_xor_sync(0xffffffffu, tm1, 2));

        float mn0 = fmaxf(mrow0, tm0 * scale);
        float mn1 = fmaxf(mrow1, tm1 * scale);
        float sf0 = __expf(mrow0 - mn0);
        float sf1 = __expf(mrow1 - mn1);
        mrow0 = mn0; mrow1 = mn1;

        float rs0 = 0.f, rs1 = 0.f;
        #pragma unroll
        for (int nt = 0; nt < 8; nt++) {
            float p0 = __expf(sacc[nt][0] * scale - mn0);
            float p1 = __expf(sacc[nt][1] * scale - mn0);
            float p2 = __expf(sacc[nt][2] * scale - mn1);
            float p3 = __expf(sacc[nt][3] * scale - mn1);
            rs0 += p0 + p1;
            rs1 += p2 + p3;
            *(float2*)&sP[r0 * VST + nt * 8 + 2 * tig] =
                make_float2(f2tf32f(p0), f2tf32f(p1));
            *(float2*)&sP[(r0 + 8) * VST + nt * 8 + 2 * tig] =
                make_float2(f2tf32f(p2), f2tf32f(p3));
        }
        rs0 += __shfl_xor_sync(0xffffffffu, rs0, 1);
        rs0 += __shfl_xor_sync(0xffffffffu, rs0, 2);
        rs1 += __shfl_xor_sync(0xffffffffu, rs1, 1);
        rs1 += __shfl_xor_sync(0xffffffffu, rs1, 2);
        lrow0 = lrow0 * sf0 + rs0;
        lrow1 = lrow1 * sf1 + rs1;

        #pragma unroll
        for (int nt = 0; nt < 16; nt++) {
            oacc[nt][0] *= sf0;
            oacc[nt][1] *= sf0;
            oacc[nt][2] *= sf1;
            oacc[nt][3] *= sf1;
        }
        __syncthreads();   // sP visible to all

        // ---- O += P V ----
        #pragma unroll
        for (int kt = 0; kt < 8; kt++) {
            uint32_t afr[4];
            afr[0] = __float_as_uint(sP[r0 * VST + kt * 8 + tig]);
            afr[1] = __float_as_uint(sP[(r0 + 8) * VST + kt * 8 + tig]);
            afr[2] = __float_as_uint(sP[r0 * VST + kt * 8 + tig + 4]);
            afr[3] = __float_as_uint(sP[(r0 + 8) * VST + kt * 8 + tig + 4]);
            #pragma unroll
            for (int nt = 0; nt < 16; nt++) {
                uint32_t b0 = __float_as_uint(sV[(nt * 8 + g) * VST + kt * 8 + tig]);
                uint32_t b1 = __float_as_uint(sV[(nt * 8 + g) * VST + kt * 8 + tig + 4]);
                mma_tf32(oacc[nt], afr, b0, b1);
            }
        }
        __syncthreads();   // all reads of sK/sV/sP done before next overwrite
    }

    // ---- epilogue: normalize and write flat O [b][n][h*128] ----
    float inv0 = 1.f / lrow0;
    float inv1 = 1.f / lrow1;
    int b = bh >> 4, h = bh & 15;
    float* Og = g_O + ((size_t)(b * SEQ + q0)) * DIM + h * DHEAD;
    #pragma unroll
    for (int nt = 0; nt < 16; nt++) {
        int col = nt * 8 + 2 * tig;
        *(float2*)(Og + (size_t)r0 * DIM + col) =
            make_float2(oacc[nt][0] * inv0, oacc[nt][1] * inv0);
        *(float2*)(Og + (size_t)(r0 + 8) * DIM + col) =
            make_float2(oacc[nt][2] * inv1, oacc[nt][3] * inv1);
    }
}

// ---------------------------------------------------------------------------
// Launch: metadata order = x, w_qkv, w_out, b_out ; output fp32 [4,2048,2048]
// ---------------------------------------------------------------------------
extern "C" void kernel_launch(void* const* d_in, const int* in_sizes, int n_in,
                              void* d_out, int out_size)
{
    const float* x     = (const float*)d_in[0];
    const float* w_qkv = (const float*)d_in[1];
    const float* w_out = (const float*)d_in[2];
    const float* b_out = (const float*)d_in[3];
    float* out = (float*)d_out;

    static bool attr_set = false;
    if (!attr_set) {
        cudaFuncSetAttribute(flash_kernel,
                             cudaFuncAttributeMaxDynamicSharedMemorySize,
                             FLASH_SMEM_BYTES);
        cudaFuncSetAttribute(gemm_nt<0>,
                             cudaFuncAttributeMaxDynamicSharedMemorySize,
                             GEMM_SMEM_BYTES);
        cudaFuncSetAttribute(gemm_nt<3>,
                             cudaFuncAttributeMaxDynamicSharedMemorySize,
                             GEMM_SMEM_BYTES);
        attr_set = true;
    }

    // QKV projection: [8192,2048] x [6144,2048]^T, scatter to Q/K/V layouts
    gemm_nt<0><<<dim3(48, 64, 1), 256, GEMM_SMEM_BYTES>>>(x, w_qkv, nullptr, nullptr, 8192, 6144, 2048);
    // RoPE in place on Q, K (writes tf32-rounded)
    rope_kernel<<<(BHTOT * SEQ * 64) / 256, 256>>>();
    // Fused attention -> g_O
    flash_kernel<<<dim3(16, 64, 1), 256, FLASH_SMEM_BYTES>>>();
    // Output projection + bias: [8192,2048] x [2048,2048]^T
    gemm_nt<3><<<dim3(16, 64, 1), 256, GEMM_SMEM_BYTES>>>(nullptr, w_out, b_out, out, 8192, DIM, DIM);
}

// round 5
// speedup vs baseline: 1.3243x; 1.3243x over previous
#include <cuda_runtime.h>
#include <cstdint>

// Problem constants
#define NHEADS 16
#define DHEAD  128
#define SEQ    2048
#define BATCH  4
#define DIM    2048
#define BHTOT  (BATCH * NHEADS)   // 64

// Scratch (device globals: allocation-free per harness rules) — ~384 MiB total
__device__ float g_Q[(size_t)BHTOT * SEQ * DHEAD];     // [bh][n][d]  tf32 (after rope)
__device__ float g_K[(size_t)BHTOT * SEQ * DHEAD];     // [bh][n][d]  tf32 (after rope)
__device__ float g_V[(size_t)BHTOT * DHEAD * SEQ];     // [bh][d][n]  tf32, transposed
__device__ float g_O[(size_t)BATCH * SEQ * DIM];       // [b][n][h*d] tf32 (flash epilogue rounds)
__device__ float g_X[(size_t)BATCH * SEQ * DIM];       // tf32 copy of x
__device__ float g_Wqkv[(size_t)3 * DIM * DIM];        // tf32 copy of w_qkv
__device__ float g_Wout[(size_t)DIM * DIM];            // tf32 copy of w_out

// ---------------------------------------------------------------------------
// TF32 / cp.async helpers
// ---------------------------------------------------------------------------
__device__ __forceinline__ uint32_t f2tf32(float f) {
    uint32_t r;
    asm("cvt.rna.tf32.f32 %0, %1;" : "=r"(r) : "f"(f));
    return r;
}
__device__ __forceinline__ float f2tf32f(float f) { return __uint_as_float(f2tf32(f)); }

__device__ __forceinline__ void mma_tf32(float* c, const uint32_t* a, uint32_t b0, uint32_t b1) {
    asm volatile(
        "mma.sync.aligned.m16n8k8.row.col.f32.tf32.tf32.f32 "
        "{%0,%1,%2,%3}, {%4,%5,%6,%7}, {%8,%9}, {%0,%1,%2,%3};\n"
        : "+f"(c[0]), "+f"(c[1]), "+f"(c[2]), "+f"(c[3])
        : "r"(a[0]), "r"(a[1]), "r"(a[2]), "r"(a[3]), "r"(b0), "r"(b1));
}

__device__ __forceinline__ void cp16(float* s, const float* g) {
    uint32_t sa = (uint32_t)__cvta_generic_to_shared(s);
    asm volatile("cp.async.cg.shared.global [%0], [%1], 16;\n" :: "r"(sa), "l"(g));
}
#define CP_COMMIT() asm volatile("cp.async.commit_group;\n" ::: "memory")
#define CP_WAIT1()  asm volatile("cp.async.wait_group 1;\n" ::: "memory")
#define CP_WAIT0()  asm volatile("cp.async.wait_group 0;\n" ::: "memory")

// ---------------------------------------------------------------------------
// Prepass: round fp32 -> tf32 bits, elementwise copy (float4).
// ---------------------------------------------------------------------------
__global__ __launch_bounds__(256)
void round_copy(const float4* __restrict__ src, float4* __restrict__ dst, int n4)
{
    int i = blockIdx.x * blockDim.x + threadIdx.x;
    if (i < n4) {
        float4 v = src[i];
        v.x = f2tf32f(v.x); v.y = f2tf32f(v.y);
        v.z = f2tf32f(v.z); v.w = f2tf32f(v.w);
        dst[i] = v;
    }
}

// ---------------------------------------------------------------------------
// NT GEMM: C[M,N] = A[M,K] * B[N,K]^T  (row-major, K contiguous).
// R3 skeleton: tile 128x128, BK=16, static smem, 2-stage cp.async pipeline.
// All inputs pre-rounded to tf32 in HBM -> mainloop is raw LDS + MMA.
// 8 warps (4 along M x 2 along N), warp 32x64 via 2x8 m16n8k8 TF32 tiles.
// MODE 0: A=g_X, B=g_Wqkv -> scatter g_Q / g_K (raw; rope rounds) / g_V (tf32)
// MODE 3: A=g_O (tf32), B=g_Wout (tf32), +bias -> d_out
// ---------------------------------------------------------------------------
#define BM 128
#define BN 128
#define BK 16
#define BKP 20

template <int MODE>
__global__ __launch_bounds__(256, 2)
void gemm_nt(const float* __restrict__ bias, float* __restrict__ Cout,
             int M, int N, int K)
{
    __shared__ float As[2][BM * BKP];
    __shared__ float Bs[2][BN * BKP];

    const int tid  = threadIdx.x;
    const int lane = tid & 31;
    const int wid  = tid >> 5;
    const int g    = lane >> 2;
    const int tig  = lane & 3;
    const int wm   = wid & 3;
    const int wn   = wid >> 2;
    const int bm   = blockIdx.y;
    const int bn   = blockIdx.x;

    const float* A = (MODE == 3) ? g_O : g_X;
    const float* B = (MODE == 3) ? g_Wout : g_Wqkv;

    float acc[2][8][4];
    #pragma unroll
    for (int mt = 0; mt < 2; mt++)
        #pragma unroll
        for (int nt = 0; nt < 8; nt++)
            #pragma unroll
            for (int i = 0; i < 4; i++) acc[mt][nt][i] = 0.f;

    const int lrow = tid >> 2;
    const int lcol = (tid & 3) << 2;
    const float* Aptr = A + (size_t)(bm * BM + lrow) * K + lcol;
    const float* Bptr = B + (size_t)(bn * BN + lrow) * K + lcol;

    const int KT = K / BK;

    #pragma unroll
    for (int it = 0; it < 2; it++) {
        cp16(&As[0][(lrow + it * 64) * BKP + lcol], Aptr + (size_t)(it * 64) * K);
        cp16(&Bs[0][(lrow + it * 64) * BKP + lcol], Bptr + (size_t)(it * 64) * K);
    }
    CP_COMMIT();

    for (int kt = 0; kt < KT; kt++) {
        const int cur = kt & 1;
        if (kt + 1 < KT) {
            const int nxt = cur ^ 1;
            const int k1 = (kt + 1) * BK;
            #pragma unroll
            for (int it = 0; it < 2; it++) {
                cp16(&As[nxt][(lrow + it * 64) * BKP + lcol], Aptr + (size_t)(it * 64) * K + k1);
                cp16(&Bs[nxt][(lrow + it * 64) * BKP + lcol], Bptr + (size_t)(it * 64) * K + k1);
            }
            CP_COMMIT();
            CP_WAIT1();
        } else {
            CP_WAIT0();
        }
        __syncthreads();

        #pragma unroll
        for (int ks = 0; ks < 2; ks++) {
            uint32_t afr[2][4];
            #pragma unroll
            for (int mt = 0; mt < 2; mt++) {
                int r0 = wm * 32 + mt * 16 + g;
                int c0 = ks * 8 + tig;
                afr[mt][0] = __float_as_uint(As[cur][r0 * BKP + c0]);
                afr[mt][1] = __float_as_uint(As[cur][(r0 + 8) * BKP + c0]);
                afr[mt][2] = __float_as_uint(As[cur][r0 * BKP + c0 + 4]);
                afr[mt][3] = __float_as_uint(As[cur][(r0 + 8) * BKP + c0 + 4]);
            }
            #pragma unroll
            for (int nt = 0; nt < 8; nt++) {
                int nr = wn * 64 + nt * 8 + g;
                int kc = ks * 8 + tig;
                uint32_t b0 = __float_as_uint(Bs[cur][nr * BKP + kc]);
                uint32_t b1 = __float_as_uint(Bs[cur][nr * BKP + kc + 4]);
                #pragma unroll
                for (int mt = 0; mt < 2; mt++)
                    mma_tf32(acc[mt][nt], afr[mt], b0, b1);
            }
        }
        __syncthreads();
    }

    #pragma unroll
    for (int mt = 0; mt < 2; mt++) {
        #pragma unroll
        for (int nt = 0; nt < 8; nt++) {
            int row0 = bm * BM + wm * 32 + mt * 16 + g;
            int col  = bn * BN + wn * 64 + nt * 8 + 2 * tig;
            #pragma unroll
            for (int rr = 0; rr < 2; rr++) {
                int row = row0 + rr * 8;
                float x0 = acc[mt][nt][rr * 2 + 0];
                float x1 = acc[mt][nt][rr * 2 + 1];
                if (MODE == 0) {
                    int b = row >> 11, pos = row & 2047;
                    int which = col >> 11, rem = col & 2047;
                    int h = rem >> 7, d = rem & 127;
                    int bhh = (b << 4) + h;
                    if (which == 2) {
                        // V: pre-round so flash mainloop is CVT-free
                        g_V[((size_t)bhh * DHEAD + d)     * SEQ + pos] = f2tf32f(x0);
                        g_V[((size_t)bhh * DHEAD + d + 1) * SEQ + pos] = f2tf32f(x1);
                    } else if (which == 0) {
                        *(float2*)(g_Q + ((size_t)bhh * SEQ + pos) * DHEAD + d) = make_float2(x0, x1);
                    } else {
                        *(float2*)(g_K + ((size_t)bhh * SEQ + pos) * DHEAD + d) = make_float2(x0, x1);
                    }
                } else {
                    *(float2*)(Cout + (size_t)row * N + col) =
                        make_float2(x0 + bias[col], x1 + bias[col + 1]);
                }
            }
        }
    }
}

// ---------------------------------------------------------------------------
// RoPE: in-place on g_Q, g_K; writes tf32-rounded bits.
// ---------------------------------------------------------------------------
__global__ __launch_bounds__(256)
void rope_kernel()
{
    int t = blockIdx.x * blockDim.x + threadIdx.x;   // 64*2048*64 threads
    int i   = t & 63;
    int pos = (t >> 6) & 2047;
    int bh  = t >> 17;
    float p = (float)(2 * i) * (1.0f / 128.0f);
    float inv_freq = powf(10000.0f, -p);
    float fr = (float)pos * inv_freq;
    float s, c;
    sincosf(fr, &s, &c);
    size_t base = ((size_t)bh * SEQ + pos) * DHEAD;

    float q1 = g_Q[base + i], q2 = g_Q[base + i + 64];
    g_Q[base + i]      = f2tf32f(q1 * c - q2 * s);
    g_Q[base + i + 64] = f2tf32f(q2 * c + q1 * s);

    float k1 = g_K[base + i], k2 = g_K[base + i + 64];
    g_K[base + i]      = f2tf32f(k1 * c - k2 * s);
    g_K[base + i + 64] = f2tf32f(k2 * c + k1 * s);
}

// ---------------------------------------------------------------------------
// Fused flash attention: per block = (q-tile of 128 rows, bh).
// 8 warps x 16 q-rows; row reductions are shfl.bfly within 4-lane groups.
// Q register-resident; K/V/Q pre-rounded tf32 in HBM -> mainloop raw LDS+MMA.
// K/V double-buffered cp.async. P tf32-pre-rounded through smem.
// Epilogue writes g_O tf32-rounded (feeds gemm<3> raw).
// ---------------------------------------------------------------------------
#define TKV 64
#define NKVT (SEQ / TKV)     // 32
#define KST 132              // smem stride for K/Q tile rows (128 cols + pad)
#define VST 68               // smem stride for V/P tile rows (64 cols + pad)
#define FLASH_SMEM_FLOATS (16896 + 17408 + 8704)
#define FLASH_SMEM_BYTES  (FLASH_SMEM_FLOATS * 4)   // 172,032

__global__ __launch_bounds__(256)
void flash_kernel()
{
    extern __shared__ float sm[];
    float* const sK0 = sm;
    float* const sK1 = sm + 8448;
    float* const sV0 = sm + 16896;
    float* const sV1 = sm + 25600;
    float* const sP  = sm + 34304;

    const int tid  = threadIdx.x;
    const int lane = tid & 31;
    const int wid  = tid >> 5;
    const int g    = lane >> 2;
    const int tig  = lane & 3;
    const int bh   = blockIdx.y;
    const int q0   = blockIdx.x * 128;
    const float scale = 0.08838834764831845f;  // 128^-0.5

    const float* Qg = g_Q + (size_t)bh * SEQ * DHEAD;
    const float* Kg = g_K + (size_t)bh * SEQ * DHEAD;
    const float* Vg = g_V + (size_t)bh * DHEAD * SEQ;

    // ---- stage Q tile (128x128) through smem, extract A-fragments ----
    #pragma unroll
    for (int i = 0; i < 16; i++) {
        int e = i * 256 + tid;            // float4 index over 128 rows x 32
        int row = e >> 5, c4 = e & 31;
        cp16(&sm[row * KST + c4 * 4], Qg + (size_t)(q0 + row) * DHEAD + c4 * 4);
    }
    CP_COMMIT();
    CP_WAIT0();
    __syncthreads();

    const int r0 = wid * 16 + g;          // this thread's first q row (local)
    uint32_t qf[16][4];
    #pragma unroll
    for (int kt = 0; kt < 16; kt++) {
        qf[kt][0] = __float_as_uint(sm[r0 * KST + kt * 8 + tig]);
        qf[kt][1] = __float_as_uint(sm[(r0 + 8) * KST + kt * 8 + tig]);
        qf[kt][2] = __float_as_uint(sm[r0 * KST + kt * 8 + tig + 4]);
        qf[kt][3] = __float_as_uint(sm[(r0 + 8) * KST + kt * 8 + tig + 4]);
    }
    __syncthreads();

    float oacc[16][4];
    #pragma unroll
    for (int nt = 0; nt < 16; nt++)
        #pragma unroll
        for (int i = 0; i < 4; i++) oacc[nt][i] = 0.f;
    float mrow0 = -1e30f, mrow1 = -1e30f;
    float lrow0 = 0.f, lrow1 = 0.f;

    // prologue: tile 0 into buffer 0
    {
        #pragma unroll
        for (int i = 0; i < 8; i++) {
            int e = i * 256 + tid;
            int kr = e >> 5, kc = e & 31;       // K: 64 rows x 32 float4
            cp16(&sK0[kr * KST + kc * 4], Kg + (size_t)kr * DHEAD + kc * 4);
            int vr = e >> 4, vc = e & 15;       // V: 128 rows x 16 float4
            cp16(&sV0[vr * VST + vc * 4], Vg + (size_t)vr * SEQ + vc * 4);
        }
        CP_COMMIT();
    }

    for (int it = 0; it < NKVT; it++) {
        const int buf = it & 1;
        const float* sK = buf ? sK1 : sK0;
        const float* sV = buf ? sV1 : sV0;

        if (it + 1 < NKVT) {
            float* dK = buf ? sK0 : sK1;
            float* dV = buf ? sV0 : sV1;
            const int kv1 = (it + 1) * TKV;
            #pragma unroll
            for (int i = 0; i < 8; i++) {
                int e = i * 256 + tid;
                int kr = e >> 5, kc = e & 31;
                cp16(&dK[kr * KST + kc * 4], Kg + (size_t)(kv1 + kr) * DHEAD + kc * 4);
                int vr = e >> 4, vc = e & 15;
                cp16(&dV[vr * VST + vc * 4], Vg + (size_t)vr * SEQ + kv1 + vc * 4);
            }
            CP_COMMIT();
            CP_WAIT1();
        } else {
            CP_WAIT0();
        }
        __syncthreads();

        // ---- S = Q K^T for this warp's 16 rows x 64 kv cols ----
        float sacc[8][4];
        #pragma unroll
        for (int nt = 0; nt < 8; nt++)
            #pragma unroll
            for (int i = 0; i < 4; i++) sacc[nt][i] = 0.f;

        #pragma unroll
        for (int kt = 0; kt < 16; kt++) {
            #pragma unroll
            for (int nt = 0; nt < 8; nt++) {
                uint32_t b0 = __float_as_uint(sK[(nt * 8 + g) * KST + kt * 8 + tig]);
                uint32_t b1 = __float_as_uint(sK[(nt * 8 + g) * KST + kt * 8 + tig + 4]);
                mma_tf32(sacc[nt], qf[kt], b0, b1);
            }
        }

        // ---- online softmax (rows r0 and r0+8) ----
        float tm0 = -1e30f, tm1 = -1e30f;
        #pragma unroll
        for (int nt = 0; nt < 8; nt++) {
            tm0 = fmaxf(tm0, fmaxf(sacc[nt][0], sacc[nt][1]));
            tm1 = fmaxf(tm1, fmaxf(sacc[nt][2], sacc[nt][3]));
        }
        tm0 = fmaxf(tm0, __shfl_xor_sync(0xffffffffu, tm0, 1));
        tm0 = fmaxf(tm0, __shfl_xor_sync(0xffffffffu, tm0, 2));
        tm1 = fmaxf(tm1, __shfl_xor_sync(0xffffffffu, tm1, 1));
        tm1 = fmaxf(tm1, __shfl_xor_sync(0xffffffffu, tm1, 2));

        float mn0 = fmaxf(mrow0, tm0 * scale);
        float mn1 = fmaxf(mrow1, tm1 * scale);
        float sf0 = __expf(mrow0 - mn0);
        float sf1 = __expf(mrow1 - mn1);
        mrow0 = mn0; mrow1 = mn1;

        float rs0 = 0.f, rs1 = 0.f;
        #pragma unroll
        for (int nt = 0; nt < 8; nt++) {
            float p0 = __expf(sacc[nt][0] * scale - mn0);
            float p1 = __expf(sacc[nt][1] * scale - mn0);
            float p2 = __expf(sacc[nt][2] * scale - mn1);
            float p3 = __expf(sacc[nt][3] * scale - mn1);
            rs0 += p0 + p1;
            rs1 += p2 + p3;
            *(float2*)&sP[r0 * VST + nt * 8 + 2 * tig] =
                make_float2(f2tf32f(p0), f2tf32f(p1));
            *(float2*)&sP[(r0 + 8) * VST + nt * 8 + 2 * tig] =
                make_float2(f2tf32f(p2), f2tf32f(p3));
        }
        rs0 += __shfl_xor_sync(0xffffffffu, rs0, 1);
        rs0 += __shfl_xor_sync(0xffffffffu, rs0, 2);
        rs1 += __shfl_xor_sync(0xffffffffu, rs1, 1);
        rs1 += __shfl_xor_sync(0xffffffffu, rs1, 2);
        lrow0 = lrow0 * sf0 + rs0;
        lrow1 = lrow1 * sf1 + rs1;

        #pragma unroll
        for (int nt = 0; nt < 16; nt++) {
            oacc[nt][0] *= sf0;
            oacc[nt][1] *= sf0;
            oacc[nt][2] *= sf1;
            oacc[nt][3] *= sf1;
        }
        __syncthreads();   // sP visible to all

        // ---- O += P V ----
        #pragma unroll
        for (int kt = 0; kt < 8; kt++) {
            uint32_t afr[4];
            afr[0] = __float_as_uint(sP[r0 * VST + kt * 8 + tig]);
            afr[1] = __float_as_uint(sP[(r0 + 8) * VST + kt * 8 + tig]);
            afr[2] = __float_as_uint(sP[r0 * VST + kt * 8 + tig + 4]);
            afr[3] = __float_as_uint(sP[(r0 + 8) * VST + kt * 8 + tig + 4]);
            #pragma unroll
            for (int nt = 0; nt < 16; nt++) {
                uint32_t b0 = __float_as_uint(sV[(nt * 8 + g) * VST + kt * 8 + tig]);
                uint32_t b1 = __float_as_uint(sV[(nt * 8 + g) * VST + kt * 8 + tig + 4]);
                mma_tf32(oacc[nt], afr, b0, b1);
            }
        }
        __syncthreads();   // all reads of sK/sV/sP done before next overwrite
    }

    // ---- epilogue: normalize, round to tf32 (feeds gemm<3> raw), write ----
    float inv0 = 1.f / lrow0;
    float inv1 = 1.f / lrow1;
    int b = bh >> 4, h = bh & 15;
    float* Og = g_O + ((size_t)(b * SEQ + q0)) * DIM + h * DHEAD;
    #pragma unroll
    for (int nt = 0; nt < 16; nt++) {
        int col = nt * 8 + 2 * tig;
        *(float2*)(Og + (size_t)r0 * DIM + col) =
            make_float2(f2tf32f(oacc[nt][0] * inv0), f2tf32f(oacc[nt][1] * inv0));
        *(float2*)(Og + (size_t)(r0 + 8) * DIM + col) =
            make_float2(f2tf32f(oacc[nt][2] * inv1), f2tf32f(oacc[nt][3] * inv1));
    }
}

// ---------------------------------------------------------------------------
// Launch: metadata order = x, w_qkv, w_out, b_out ; output fp32 [4,2048,2048]
// ---------------------------------------------------------------------------
extern "C" void kernel_launch(void* const* d_in, const int* in_sizes, int n_in,
                              void* d_out, int out_size)
{
    const float* x     = (const float*)d_in[0];
    const float* w_qkv = (const float*)d_in[1];
    const float* w_out = (const float*)d_in[2];
    const float* b_out = (const float*)d_in[3];
    float* out = (float*)d_out;

    static bool attr_set = false;
    if (!attr_set) {
        cudaFuncSetAttribute(flash_kernel,
                             cudaFuncAttributeMaxDynamicSharedMemorySize,
                             FLASH_SMEM_BYTES);
        attr_set = true;
    }

    float* gx; float* gwq; float* gwo;
    cudaGetSymbolAddress((void**)&gx,  g_X);
    cudaGetSymbolAddress((void**)&gwq, g_Wqkv);
    cudaGetSymbolAddress((void**)&gwo, g_Wout);

    // Prepass: tf32-round inputs into device globals (single rounding point).
    const int n4x = (BATCH * SEQ * DIM) / 4;          // 4,194,304
    const int n4q = (3 * DIM * DIM) / 4;              // 3,145,728
    const int n4o = (DIM * DIM) / 4;                  // 1,048,576
    round_copy<<<(n4x + 255) / 256, 256>>>((const float4*)x,     (float4*)gx,  n4x);
    round_copy<<<(n4q + 255) / 256, 256>>>((const float4*)w_qkv, (float4*)gwq, n4q);
    round_copy<<<(n4o + 255) / 256, 256>>>((const float4*)w_out, (float4*)gwo, n4o);

    // QKV projection: [8192,2048] x [6144,2048]^T, scatter to Q/K/V layouts
    gemm_nt<0><<<dim3(48, 64, 1), 256>>>(nullptr, nullptr, 8192, 6144, 2048);
    // RoPE in place on Q, K (writes tf32-rounded)
    rope_kernel<<<(BHTOT * SEQ * 64) / 256, 256>>>();
    // Fused attention -> g_O (tf32-rounded)
    flash_kernel<<<dim3(16, 64, 1), 256, FLASH_SMEM_BYTES>>>();
    // Output projection + bias: [8192,2048] x [2048,2048]^T
    gemm_nt<3><<<dim3(16, 64, 1), 256>>>(b_out, out, 8192, DIM, DIM);
}